// round 16
// baseline (speedup 1.0000x reference)
#include <cuda_runtime.h>
#include <cuda_fp16.h>

// Active region: x0,y0,z0 in [127,254] (positions uniform [0,1) -> gx in [127.5,255)).
// Full 2x2x2 corner cube per voxel: 8 x fp16 = 16 B. 128^3 voxels = 33.5 MB.
#define CUBE_ELEMS (1 << 21)
__device__ uint4 g_cube[CUBE_ELEMS];

__device__ __forceinline__ unsigned pack2(float lo, float hi) {
    __half2 h = __halves2half2(__float2half_rn(lo), __float2half_rn(hi));
    return *reinterpret_cast<unsigned*>(&h);
}

__global__ void __launch_bounds__(256) repack_cube_kernel(const float* __restrict__ g)
{
    int tid = blockIdx.x * 256 + threadIdx.x;      // 2,097,152 threads
    int z = 127 + (tid & 127);
    int y = 127 + ((tid >> 7) & 127);
    int x = 127 + (tid >> 14);                      // x,y,z <= 254; +1 <= 255 safe

    const float* p = g + ((x << 16) | (y << 8) | z);
    float c000 = __ldg(p);             float c001 = __ldg(p + 1);
    float c010 = __ldg(p + 256);       float c011 = __ldg(p + 257);
    float c100 = __ldg(p + 65536);     float c101 = __ldg(p + 65537);
    float c110 = __ldg(p + 65792);     float c111 = __ldg(p + 65793);

    uint4 q;
    q.x = pack2(c000, c001);   // (x0,y0) z-pair
    q.y = pack2(c010, c011);   // (x0,y1)
    q.z = pack2(c100, c101);   // (x1,y0)
    q.w = pack2(c110, c111);   // (x1,y1)
    g_cube[tid] = q;
}

__device__ __forceinline__ float lerp_cube(uint4 q, float xd, float yd, float zd)
{
    float2 a = __half22float2(*reinterpret_cast<__half2*>(&q.x)); // (c000,c001)
    float2 b = __half22float2(*reinterpret_cast<__half2*>(&q.y)); // (c010,c011)
    float2 c = __half22float2(*reinterpret_cast<__half2*>(&q.z)); // (c100,c101)
    float2 d = __half22float2(*reinterpret_cast<__half2*>(&q.w)); // (c110,c111)

    float c00 = fmaf(a.y - a.x, zd, a.x);
    float c01 = fmaf(b.y - b.x, zd, b.x);
    float c10 = fmaf(c.y - c.x, zd, c.x);
    float c11 = fmaf(d.y - d.x, zd, d.x);

    float c0 = fmaf(c01 - c00, yd, c00);
    float c1 = fmaf(c11 - c10, yd, c10);
    return fmaf(c1 - c0, xd, c0);
}

// Exact fp32 path for out-of-region points; recomputes everything from raw position
// so the hot path doesn't carry extra live registers. Never taken for uniform [0,1) data.
__device__ __noinline__ float lerp_fallback(const float* __restrict__ grid,
                                            float px, float py, float pz)
{
    const float scale = 0.5f * 255.0f;
    float gx = (px + 1.0f) * scale;
    float gy = (py + 1.0f) * scale;
    float gz = (pz + 1.0f) * scale;
    float fx = floorf(gx), fy = floorf(gy), fz = floorf(gz);
    float xd = gx - fx, yd = gy - fy, zd = gz - fz;
    int x0 = min(max((int)fx, 0), 255);
    int y0 = min(max((int)fy, 0), 255);
    int z0 = min(max((int)fz, 0), 255);
    int x1 = min(x0 + 1, 255), y1 = min(y0 + 1, 255), z1 = min(z0 + 1, 255);
    int bx0 = x0 << 16, bx1 = x1 << 16, by0 = y0 << 8, by1 = y1 << 8;
    float c000 = __ldg(&grid[bx0 + by0 + z0]);
    float c001 = __ldg(&grid[bx0 + by0 + z1]);
    float c010 = __ldg(&grid[bx0 + by1 + z0]);
    float c011 = __ldg(&grid[bx0 + by1 + z1]);
    float c100 = __ldg(&grid[bx1 + by0 + z0]);
    float c101 = __ldg(&grid[bx1 + by0 + z1]);
    float c110 = __ldg(&grid[bx1 + by1 + z0]);
    float c111 = __ldg(&grid[bx1 + by1 + z1]);
    float c00 = fmaf(c001 - c000, zd, c000);
    float c01 = fmaf(c011 - c010, zd, c010);
    float c10 = fmaf(c101 - c100, zd, c100);
    float c11 = fmaf(c111 - c110, zd, c110);
    float c0 = fmaf(c01 - c00, yd, c00);
    float c1 = fmaf(c11 - c10, yd, c10);
    return fmaf(c1 - c0, xd, c0);
}

__device__ __forceinline__ float sigmoidf(float v)
{
    return 1.0f / (1.0f + __expf(-v));
}

// 1024 points per 256-thread block: 4 points per thread for 4x gather MLP.
__global__ void __launch_bounds__(256) trilerp_sigmoid_kernel(
    const float* __restrict__ positions,   // [N,3]
    const float* __restrict__ grid,        // original fp32 grid (fallback path)
    float* __restrict__ out,               // [N]
    int n)
{
    __shared__ float sp[3072];             // 1024 points x 3
    int t = threadIdx.x;
    int pbase = blockIdx.x * 1024;
    int fbase = pbase * 3;

    if (fbase + 3072 <= n * 3) {
        const float4* src = (const float4*)(positions + fbase);
        #pragma unroll
        for (int k = 0; k < 3; k++)        // 768 float4 loads
            ((float4*)sp)[t + 256 * k] = __ldcs(src + t + 256 * k);
    } else {
        for (int k = t; k < 3072 && fbase + k < n * 3; k += 256)
            sp[k] = positions[fbase + k];
    }
    __syncthreads();

    const float scale = 0.5f * 255.0f;

    float xd[4], yd[4], zd[4];
    int   idx[4];
    bool  ok[4], valid[4];

    #pragma unroll
    for (int k = 0; k < 4; k++) {
        int slot = 256 * k + t;            // point slot within block
        valid[k] = (pbase + slot) < n;
        float px = sp[3 * slot + 0];
        float py = sp[3 * slot + 1];
        float pz = sp[3 * slot + 2];

        float gx = (px + 1.0f) * scale;
        float gy = (py + 1.0f) * scale;
        float gz = (pz + 1.0f) * scale;
        float fx = floorf(gx), fy = floorf(gy), fz = floorf(gz);
        xd[k] = gx - fx; yd[k] = gy - fy; zd[k] = gz - fz;

        int x0 = (int)fx, y0 = (int)fy, z0 = (int)fz;
        ok[k] = ((unsigned)(x0 - 127) < 128u) &
                ((unsigned)(y0 - 127) < 128u) &
                ((unsigned)(z0 - 127) < 128u);
        int cx = min(max(x0 - 127, 0), 127);
        int cy = min(max(y0 - 127, 0), 127);
        int cz = min(max(z0 - 127, 0), 127);
        idx[k] = (cx << 14) | (cy << 7) | cz;
    }

    // issue all 4 independent gathers before any dependent math
    uint4 q[4];
    #pragma unroll
    for (int k = 0; k < 4; k++)
        if (valid[k]) q[k] = __ldg(&g_cube[idx[k]]);

    #pragma unroll
    for (int k = 0; k < 4; k++) {
        if (!valid[k]) continue;
        int slot = 256 * k + t;
        float v;
        if (ok[k]) {
            v = lerp_cube(q[k], xd[k], yd[k], zd[k]);
        } else {
            v = lerp_fallback(grid, sp[3 * slot + 0], sp[3 * slot + 1], sp[3 * slot + 2]);
        }
        __stcs(&out[pbase + slot], sigmoidf(v));
    }
}

extern "C" void kernel_launch(void* const* d_in, const int* in_sizes, int n_in,
                              void* d_out, int out_size)
{
    const float* positions = (const float*)d_in[0];
    const float* grid      = (const float*)d_in[1];
    float* out             = (float*)d_out;

    int n = in_sizes[0] / 3;

    repack_cube_kernel<<<CUBE_ELEMS / 256, 256>>>(grid);

    int blocks = (n + 1023) / 1024;
    trilerp_sigmoid_kernel<<<blocks, 256>>>(positions, grid, out, n);
}